// round 5
// baseline (speedup 1.0000x reference)
#include <cuda_runtime.h>
#include <cuda_bf16.h>
#include <cstdint>

// LuongAttention: O[b] = (Q Eᵀ) E == Q (EᵀE).  G = EᵀE per batch (128x128).
// HMMA bf16 split-precision (hi·hi + hi·lo + lo·hi, fp32 accum, err ~4e-6).
// R5: no staging transpose (ldmatrix.trans), M-split CTAs for 2/SM overlap,
// G pre-split into bf16 planes by the reduce kernel.  B=8, T=2048, D=128.

#define BB 8
#define NSPLIT 16
#define RSTRIDE 272                     // plane row stride, bytes (16 mod 128)
#define PLANE128 (128 * RSTRIDE)        // 34816 B
#define PLANE64  (64 * RSTRIDE)         // 17408 B

__device__ float g_part[BB * NSPLIT * 128 * 128];          // 8 MB partials
__device__ uint4 g_hiP[BB * PLANE128 / 16];                 // G hi planes (RSTRIDE layout)
__device__ uint4 g_loP[BB * PLANE128 / 16];                 // G lo planes

// ---------------- helpers ----------------
__device__ __forceinline__ uint32_t smem_u32(const void* p) {
    uint32_t a;
    asm("{ .reg .u64 t; cvta.to.shared.u64 t, %1; cvt.u32.u64 %0, t; }"
        : "=r"(a) : "l"(p));
    return a;
}
__device__ __forceinline__ void ldsm_x4(uint32_t (&r)[4], uint32_t addr) {
    asm volatile("ldmatrix.sync.aligned.m8n8.x4.shared.b16 {%0,%1,%2,%3}, [%4];"
                 : "=r"(r[0]), "=r"(r[1]), "=r"(r[2]), "=r"(r[3]) : "r"(addr));
}
__device__ __forceinline__ void ldsm_x4_t(uint32_t (&r)[4], uint32_t addr) {
    asm volatile("ldmatrix.sync.aligned.m8n8.x4.trans.shared.b16 {%0,%1,%2,%3}, [%4];"
                 : "=r"(r[0]), "=r"(r[1]), "=r"(r[2]), "=r"(r[3]) : "r"(addr));
}
__device__ __forceinline__ void mma16816(float (&d)[4], const uint32_t (&a)[4],
                                         uint32_t b0, uint32_t b1) {
    asm volatile(
        "mma.sync.aligned.m16n8k16.row.col.f32.bf16.bf16.f32 "
        "{%0,%1,%2,%3}, {%4,%5,%6,%7}, {%8,%9}, {%0,%1,%2,%3};"
        : "+f"(d[0]), "+f"(d[1]), "+f"(d[2]), "+f"(d[3])
        : "r"(a[0]), "r"(a[1]), "r"(a[2]), "r"(a[3]), "r"(b0), "r"(b1));
}
__device__ __forceinline__ void split2(float f0, float f1, uint32_t& hi, uint32_t& lo) {
    asm("cvt.rn.bf16x2.f32 %0, %1, %2;" : "=r"(hi) : "f"(f1), "f"(f0));
    float h0 = __uint_as_float(hi << 16);
    float h1 = __uint_as_float(hi & 0xffff0000u);
    asm("cvt.rn.bf16x2.f32 %0, %1, %2;" : "=r"(lo) : "f"(f1 - h1), "f"(f0 - h0));
}

// Warp 32x32 GEMM over K=128.  TRANS=true: planes stored [k][m]/[k][n]
// (ldmatrix.trans); false: stored [m][k]/[n][k].
template <bool TRANS>
__device__ __forceinline__ void warp_gemm32(uint32_t aHi, uint32_t aLo,
                                            uint32_t bHi, uint32_t bLo,
                                            int wm, int wn, int lid,
                                            float (&acc)[2][4][4]) {
    // Per-lane base offsets (k0 added per step).
    uint32_t aRow, aCol, bRow, bCol;
    if (TRANS) {
        aRow = (lid & 7) + ((lid >> 4) << 3);          // k component
        aCol = ((lid >> 3) & 1) << 3;                  // m component
        bRow = (lid & 7) + (((lid >> 3) & 1) << 3);    // k
        bCol = (lid >> 4) << 3;                        // n
    } else {
        aRow = lid & 15;                               // m
        aCol = (lid >> 4) << 3;                        // k
        bRow = ((lid >> 4) << 3) + (lid & 7);          // n
        bCol = ((lid >> 3) & 1) << 3;                  // k
    }

#pragma unroll
    for (int kk = 0; kk < 8; kk++) {
        const int k0 = kk * 16;
        uint32_t Ah[2][4], Al[2][4], Bh[2][4], Bl[2][4];
#pragma unroll
        for (int mi = 0; mi < 2; mi++) {
            uint32_t off;
            if (TRANS)
                off = (uint32_t)(k0 + aRow) * RSTRIDE + (uint32_t)(wm + mi * 16 + aCol) * 2;
            else
                off = (uint32_t)(wm + mi * 16 + aRow) * RSTRIDE + (uint32_t)(k0 + aCol) * 2;
            if (TRANS) { ldsm_x4_t(Ah[mi], aHi + off); ldsm_x4_t(Al[mi], aLo + off); }
            else       { ldsm_x4 (Ah[mi], aHi + off); ldsm_x4 (Al[mi], aLo + off); }
        }
#pragma unroll
        for (int np = 0; np < 2; np++) {
            uint32_t off;
            if (TRANS)
                off = (uint32_t)(k0 + bRow) * RSTRIDE + (uint32_t)(wn + np * 16 + bCol) * 2;
            else
                off = (uint32_t)(wn + np * 16 + bRow) * RSTRIDE + (uint32_t)(k0 + bCol) * 2;
            if (TRANS) { ldsm_x4_t(Bh[np], bHi + off); ldsm_x4_t(Bl[np], bLo + off); }
            else       { ldsm_x4 (Bh[np], bHi + off); ldsm_x4 (Bl[np], bLo + off); }
        }
#pragma unroll
        for (int mi = 0; mi < 2; mi++)
#pragma unroll
            for (int nj = 0; nj < 4; nj++) {
                const int np = nj >> 1, pr = (nj & 1) << 1;
                mma16816(acc[mi][nj], Ah[mi], Bh[np][pr], Bh[np][pr + 1]);
                mma16816(acc[mi][nj], Ah[mi], Bl[np][pr], Bl[np][pr + 1]);
                mma16816(acc[mi][nj], Al[mi], Bh[np][pr], Bh[np][pr + 1]);
            }
    }
}

__device__ __forceinline__ void warp_epilogue32(float* outp, int wm, int wn, int lid,
                                                float (&acc)[2][4][4]) {
    const int g = lid >> 2, tig = lid & 3;
#pragma unroll
    for (int mi = 0; mi < 2; mi++)
#pragma unroll
        for (int nj = 0; nj < 4; nj++) {
            const int row = wm + mi * 16 + g;
            const int col = wn + nj * 8 + 2 * tig;
            *(float2*)(outp + row * 128 + col) =
                make_float2(acc[mi][nj][0], acc[mi][nj][1]);
            *(float2*)(outp + (row + 8) * 128 + col) =
                make_float2(acc[mi][nj][2], acc[mi][nj][3]);
        }
}

// ---------------------------------------------------------------------------
// Kernel 1: partial EᵀE.  Grid (2*NSPLIT, BB); bx = sp*2+half.
// Planes stored [t][d] directly from coalesced loads; ldmatrix.trans supplies
// the transpose.  CTA computes 64 rows (half) x 128 cols of G_sp.
// ---------------------------------------------------------------------------
__global__ __launch_bounds__(256, 2) void ete_hmma(const float* __restrict__ enc) {
    extern __shared__ char smem[];
    const uint32_t sb = smem_u32(smem);
    const int tid = threadIdx.x, wid = tid >> 5, lid = tid & 31;
    const int sp = blockIdx.x >> 1, half = blockIdx.x & 1, b = blockIdx.y;

    // Load + split chunk [t=128][d=128] fp32 -> hi/lo planes [t][d].
    const float4* src = (const float4*)(enc + (size_t)(b * NSPLIT + sp) * 128 * 128);
#pragma unroll
    for (int v = 0; v < 16; v++) {
        int idx = tid + v * 256;
        int t = idx >> 5, d4 = idx & 31;
        float4 q = src[idx];
        uint32_t h0, l0, h1, l1;
        split2(q.x, q.y, h0, l0);
        split2(q.z, q.w, h1, l1);
        uint32_t off = (uint32_t)t * RSTRIDE + (uint32_t)d4 * 8;
        *(uint2*)(smem + off) = make_uint2(h0, h1);
        *(uint2*)(smem + PLANE128 + off) = make_uint2(l0, l1);
    }
    __syncthreads();

    const int wm = half * 64 + (wid >> 2) * 32, wn = (wid & 3) * 32;
    float acc[2][4][4];
#pragma unroll
    for (int mi = 0; mi < 2; mi++)
#pragma unroll
        for (int nj = 0; nj < 4; nj++)
#pragma unroll
            for (int r = 0; r < 4; r++) acc[mi][nj][r] = 0.0f;

    warp_gemm32<true>(sb, sb + PLANE128, sb, sb + PLANE128, wm, wn, lid, acc);
    warp_epilogue32(g_part + ((size_t)(b * NSPLIT + sp) << 14), wm, wn, lid, acc);
}

// ---------------------------------------------------------------------------
// Kernel 2: reduce partials AND pre-split G into bf16 hi/lo planes laid out
// exactly as qg's smem wants them (row stride RSTRIDE).
// One thread = one d-pair of one (b, j) row.  65536 pairs total.
// ---------------------------------------------------------------------------
__global__ __launch_bounds__(256) void reduce_g() {
    const int e2 = blockIdx.x * 256 + threadIdx.x;  // 0..65535
    const int b = e2 >> 13;
    const int r = e2 & 8191;
    const int j = r >> 6, d2 = r & 63;
    const float2* base =
        (const float2*)(g_part + ((size_t)b << 18) + j * 128) + d2;
    float sx = 0.f, sy = 0.f;
#pragma unroll
    for (int sp = 0; sp < NSPLIT; sp++) {
        float2 v = base[sp << 13];                  // +sp*16384 floats
        sx += v.x; sy += v.y;
    }
    uint32_t hi, lo;
    split2(sx, sy, hi, lo);
    const uint32_t w = (uint32_t)b * (PLANE128 / 4) + (uint32_t)j * (RSTRIDE / 4) + d2;
    ((uint32_t*)g_hiP)[w] = hi;
    ((uint32_t*)g_loP)[w] = lo;
}

// ---------------------------------------------------------------------------
// Kernel 3: O_tile(64x128) = Q_tile @ G[b].  Grid (32, BB).
// Q split on the fly; G planes raw-copied (already split + laid out).
// ---------------------------------------------------------------------------
#define QG_QHI 0
#define QG_QLO PLANE64
#define QG_GHI (2 * PLANE64)
#define QG_GLO (2 * PLANE64 + PLANE128)
#define QG_SZ  (2 * PLANE64 + 2 * PLANE128)   // 104448

__global__ __launch_bounds__(256, 2) void qg_hmma(const float* __restrict__ dec,
                                                  float* __restrict__ out) {
    extern __shared__ char smem[];
    const uint32_t sb = smem_u32(smem);
    const int tid = threadIdx.x, wid = tid >> 5, lid = tid & 31;
    const int b = blockIdx.y, qt = blockIdx.x;

    // Q tile [64 q][128 d] -> hi/lo planes.
    const float4* qsrc = (const float4*)(dec + ((size_t)(b * 32 + qt) << 13));
#pragma unroll
    for (int v = 0; v < 8; v++) {
        int idx = tid + v * 256;
        int row = idx >> 5, d4 = idx & 31;
        float4 q = qsrc[idx];
        uint32_t h0, l0, h1, l1;
        split2(q.x, q.y, h0, l0);
        split2(q.z, q.w, h1, l1);
        uint32_t off = (uint32_t)row * RSTRIDE + (uint32_t)d4 * 8;
        *(uint2*)(smem + QG_QHI + off) = make_uint2(h0, h1);
        *(uint2*)(smem + QG_QLO + off) = make_uint2(l0, l1);
    }
    // G planes: raw uint4 copy (2176 per plane).
    const uint4* ghs = g_hiP + (size_t)b * (PLANE128 / 16);
    const uint4* gls = g_loP + (size_t)b * (PLANE128 / 16);
    uint4* ghd = (uint4*)(smem + QG_GHI);
    uint4* gld = (uint4*)(smem + QG_GLO);
    for (int i = tid; i < PLANE128 / 16; i += 256) {
        ghd[i] = ghs[i];
        gld[i] = gls[i];
    }
    __syncthreads();

    const int wm = (wid >> 2) * 32, wn = (wid & 3) * 32;
    float acc[2][4][4];
#pragma unroll
    for (int mi = 0; mi < 2; mi++)
#pragma unroll
        for (int nj = 0; nj < 4; nj++)
#pragma unroll
            for (int r = 0; r < 4; r++) acc[mi][nj][r] = 0.0f;

    warp_gemm32<false>(sb + QG_QHI, sb + QG_QLO, sb + QG_GHI, sb + QG_GLO,
                       wm, wn, lid, acc);
    warp_epilogue32(out + ((size_t)(b * 32 + qt) << 13), wm, wn, lid, acc);
}

// ---------------------------------------------------------------------------
// Launch
// ---------------------------------------------------------------------------
extern "C" void kernel_launch(void* const* d_in, const int* in_sizes, int n_in,
                              void* d_out, int out_size) {
    const float* enc = (const float*)d_in[0];
    const float* dec = (const float*)d_in[1];
    float* out = (float*)d_out;

    cudaFuncSetAttribute(ete_hmma, cudaFuncAttributeMaxDynamicSharedMemorySize,
                         2 * PLANE128);
    cudaFuncSetAttribute(qg_hmma, cudaFuncAttributeMaxDynamicSharedMemorySize,
                         QG_SZ);

    ete_hmma<<<dim3(2 * NSPLIT, BB), 256, 2 * PLANE128>>>(enc);
    reduce_g<<<256, 256>>>();
    qg_hmma<<<dim3(32, BB), 256, QG_SZ>>>(dec, out);
}

// round 6
// speedup vs baseline: 1.0148x; 1.0148x over previous
#include <cuda_runtime.h>
#include <cuda_bf16.h>
#include <cstdint>

// LuongAttention: O[b] = (Q Eᵀ) E == Q (EᵀE).  G = EᵀE per batch (128x128).
// HMMA bf16 split-precision (hi·hi + hi·lo + lo·hi, fp32 accum, err ~6e-6).
// R6: intra-CTA software pipeline — split/store and MMA interleaved in two
// K-stages so tensor work hides conversion/store latency (co-resident CTAs
// run in lockstep, so only intra-CTA overlap helps).  B=8, T=2048, D=128.

#define BB 8
#define NSPLIT 16
#define RSTRIDE 272                     // plane row stride, bytes
#define PLANE128 (128 * RSTRIDE)        // 34816 B
#define PLANE64  (64 * RSTRIDE)         // 17408 B

__device__ float g_part[BB * NSPLIT * 128 * 128];   // 8 MB partials
__device__ uint32_t g_hiD[BB * 128 * 64];           // G hi plane, dense [j][d] bf16
__device__ uint32_t g_loD[BB * 128 * 64];           // G lo plane, dense

// ---------------- helpers ----------------
__device__ __forceinline__ uint32_t smem_u32(const void* p) {
    uint32_t a;
    asm("{ .reg .u64 t; cvta.to.shared.u64 t, %1; cvt.u32.u64 %0, t; }"
        : "=r"(a) : "l"(p));
    return a;
}
__device__ __forceinline__ void ldsm_x4(uint32_t (&r)[4], uint32_t addr) {
    asm volatile("ldmatrix.sync.aligned.m8n8.x4.shared.b16 {%0,%1,%2,%3}, [%4];"
                 : "=r"(r[0]), "=r"(r[1]), "=r"(r[2]), "=r"(r[3]) : "r"(addr));
}
__device__ __forceinline__ void ldsm_x4_t(uint32_t (&r)[4], uint32_t addr) {
    asm volatile("ldmatrix.sync.aligned.m8n8.x4.trans.shared.b16 {%0,%1,%2,%3}, [%4];"
                 : "=r"(r[0]), "=r"(r[1]), "=r"(r[2]), "=r"(r[3]) : "r"(addr));
}
__device__ __forceinline__ void mma16816(float (&d)[4], const uint32_t (&a)[4],
                                         uint32_t b0, uint32_t b1) {
    asm volatile(
        "mma.sync.aligned.m16n8k16.row.col.f32.bf16.bf16.f32 "
        "{%0,%1,%2,%3}, {%4,%5,%6,%7}, {%8,%9}, {%0,%1,%2,%3};"
        : "+f"(d[0]), "+f"(d[1]), "+f"(d[2]), "+f"(d[3])
        : "r"(a[0]), "r"(a[1]), "r"(a[2]), "r"(a[3]), "r"(b0), "r"(b1));
}
__device__ __forceinline__ void split2(float f0, float f1, uint32_t& hi, uint32_t& lo) {
    asm("cvt.rn.bf16x2.f32 %0, %1, %2;" : "=r"(hi) : "f"(f1), "f"(f0));
    float h0 = __uint_as_float(hi << 16);
    float h1 = __uint_as_float(hi & 0xffff0000u);
    asm("cvt.rn.bf16x2.f32 %0, %1, %2;" : "=r"(lo) : "f"(f1 - h1), "f"(f0 - h0));
}

// Warp 32x32 GEMM over k-steps [kk0, kk1).  TRANS: planes stored [k][m]/[k][n].
template <bool TRANS>
__device__ __forceinline__ void warp_gemm32(uint32_t aHi, uint32_t aLo,
                                            uint32_t bHi, uint32_t bLo,
                                            int wm, int wn, int lid,
                                            int kk0, int kk1,
                                            float (&acc)[2][4][4]) {
    uint32_t aRow, aCol, bRow, bCol;
    if (TRANS) {
        aRow = (lid & 7) + ((lid >> 4) << 3);
        aCol = ((lid >> 3) & 1) << 3;
        bRow = (lid & 7) + (((lid >> 3) & 1) << 3);
        bCol = (lid >> 4) << 3;
    } else {
        aRow = lid & 15;
        aCol = (lid >> 4) << 3;
        bRow = ((lid >> 4) << 3) + (lid & 7);
        bCol = ((lid >> 3) & 1) << 3;
    }

#pragma unroll
    for (int kk = kk0; kk < kk1; kk++) {
        const int k0 = kk * 16;
        uint32_t Ah[2][4], Al[2][4], Bh[2][4], Bl[2][4];
#pragma unroll
        for (int mi = 0; mi < 2; mi++) {
            uint32_t off;
            if (TRANS)
                off = (uint32_t)(k0 + aRow) * RSTRIDE + (uint32_t)(wm + mi * 16 + aCol) * 2;
            else
                off = (uint32_t)(wm + mi * 16 + aRow) * RSTRIDE + (uint32_t)(k0 + aCol) * 2;
            if (TRANS) { ldsm_x4_t(Ah[mi], aHi + off); ldsm_x4_t(Al[mi], aLo + off); }
            else       { ldsm_x4 (Ah[mi], aHi + off); ldsm_x4 (Al[mi], aLo + off); }
        }
#pragma unroll
        for (int np = 0; np < 2; np++) {
            uint32_t off;
            if (TRANS)
                off = (uint32_t)(k0 + bRow) * RSTRIDE + (uint32_t)(wn + np * 16 + bCol) * 2;
            else
                off = (uint32_t)(wn + np * 16 + bRow) * RSTRIDE + (uint32_t)(k0 + bCol) * 2;
            if (TRANS) { ldsm_x4_t(Bh[np], bHi + off); ldsm_x4_t(Bl[np], bLo + off); }
            else       { ldsm_x4 (Bh[np], bHi + off); ldsm_x4 (Bl[np], bLo + off); }
        }
#pragma unroll
        for (int mi = 0; mi < 2; mi++)
#pragma unroll
            for (int nj = 0; nj < 4; nj++) {
                const int np = nj >> 1, pr = (nj & 1) << 1;
                mma16816(acc[mi][nj], Ah[mi], Bh[np][pr], Bh[np][pr + 1]);
                mma16816(acc[mi][nj], Ah[mi], Bl[np][pr], Bl[np][pr + 1]);
                mma16816(acc[mi][nj], Al[mi], Bh[np][pr], Bh[np][pr + 1]);
            }
    }
}

__device__ __forceinline__ void warp_epilogue32(float* outp, int wm, int wn, int lid,
                                                float (&acc)[2][4][4]) {
    const int g = lid >> 2, tig = lid & 3;
#pragma unroll
    for (int mi = 0; mi < 2; mi++)
#pragma unroll
        for (int nj = 0; nj < 4; nj++) {
            const int row = wm + mi * 16 + g;
            const int col = wn + nj * 8 + 2 * tig;
            *(float2*)(outp + row * 128 + col) =
                make_float2(acc[mi][nj][0], acc[mi][nj][1]);
            *(float2*)(outp + (row + 8) * 128 + col) =
                make_float2(acc[mi][nj][2], acc[mi][nj][3]);
        }
}

// ---------------------------------------------------------------------------
// Kernel 1: partial EᵀE, pipelined.  Grid (2*NSPLIT, BB); bx = sp*2+half.
// Planes [t][d]; ldmatrix.trans supplies the transpose.  Stage0 = t<64.
// ---------------------------------------------------------------------------
__global__ __launch_bounds__(256, 2) void ete_hmma(const float* __restrict__ enc) {
    extern __shared__ char smem[];
    const uint32_t sb = smem_u32(smem);
    const int tid = threadIdx.x, wid = tid >> 5, lid = tid & 31;
    const int sp = blockIdx.x >> 1, half = blockIdx.x & 1, b = blockIdx.y;

    // All loads issued up front.
    const float4* src = (const float4*)(enc + (size_t)(b * NSPLIT + sp) * 128 * 128);
    float4 q[16];
#pragma unroll
    for (int v = 0; v < 16; v++) q[v] = src[tid + v * 256];

    const int wm = half * 64 + (wid >> 2) * 32, wn = (wid & 3) * 32;
    float acc[2][4][4];
#pragma unroll
    for (int mi = 0; mi < 2; mi++)
#pragma unroll
        for (int nj = 0; nj < 4; nj++)
#pragma unroll
            for (int r = 0; r < 4; r++) acc[mi][nj][r] = 0.0f;

    // Stage 0: tokens t<64  (v = 0..7; t = v*8 + wid).
#pragma unroll
    for (int v = 0; v < 8; v++) {
        int idx = tid + v * 256;
        int t = idx >> 5, d4 = idx & 31;
        uint32_t h0, l0, h1, l1;
        split2(q[v].x, q[v].y, h0, l0);
        split2(q[v].z, q[v].w, h1, l1);
        uint32_t off = (uint32_t)t * RSTRIDE + (uint32_t)d4 * 8;
        *(uint2*)(smem + off) = make_uint2(h0, h1);
        *(uint2*)(smem + PLANE128 + off) = make_uint2(l0, l1);
    }
    __syncthreads();

    // Stage 1 stores (t>=64) overlap MMA on k = 0..63.
#pragma unroll
    for (int v = 8; v < 16; v++) {
        int idx = tid + v * 256;
        int t = idx >> 5, d4 = idx & 31;
        uint32_t h0, l0, h1, l1;
        split2(q[v].x, q[v].y, h0, l0);
        split2(q[v].z, q[v].w, h1, l1);
        uint32_t off = (uint32_t)t * RSTRIDE + (uint32_t)d4 * 8;
        *(uint2*)(smem + off) = make_uint2(h0, h1);
        *(uint2*)(smem + PLANE128 + off) = make_uint2(l0, l1);
    }
    warp_gemm32<true>(sb, sb + PLANE128, sb, sb + PLANE128, wm, wn, lid, 0, 4, acc);
    __syncthreads();
    warp_gemm32<true>(sb, sb + PLANE128, sb, sb + PLANE128, wm, wn, lid, 4, 8, acc);

    warp_epilogue32(g_part + ((size_t)(b * NSPLIT + sp) << 14), wm, wn, lid, acc);
}

// ---------------------------------------------------------------------------
// Kernel 2: reduce partials, output dense bf16 hi/lo planes [b][j][d].
// ---------------------------------------------------------------------------
__global__ __launch_bounds__(256) void reduce_g() {
    const int e2 = blockIdx.x * 256 + threadIdx.x;  // 0..65535 (b, j, d-pair)
    const int b = e2 >> 13;
    const int r = e2 & 8191;                         // j*64 + d2
    const int j = r >> 6, d2 = r & 63;
    const float2* base =
        (const float2*)(g_part + ((size_t)b << 18) + j * 128) + d2;
    float sx = 0.f, sy = 0.f;
#pragma unroll
    for (int sp = 0; sp < NSPLIT; sp++) {
        float2 v = base[sp << 13];
        sx += v.x; sy += v.y;
    }
    uint32_t hi, lo;
    split2(sx, sy, hi, lo);
    g_hiD[e2] = hi;
    g_loD[e2] = lo;
}

// ---------------------------------------------------------------------------
// Kernel 3: O_tile(64x128) = Q_tile @ G[b], pipelined over d-halves.
// Stage membership: Q float4 d-cols depend only on (tid&31); G uint4 d-half
// depends only on (tid&8).  Grid (32, BB).
// ---------------------------------------------------------------------------
#define QG_QHI 0
#define QG_QLO PLANE64
#define QG_GHI (2 * PLANE64)
#define QG_GLO (2 * PLANE64 + PLANE128)
#define QG_SZ  (2 * PLANE64 + 2 * PLANE128)   // 104448

__global__ __launch_bounds__(256, 2) void qg_hmma(const float* __restrict__ dec,
                                                  float* __restrict__ out) {
    extern __shared__ char smem[];
    const uint32_t sb = smem_u32(smem);
    const int tid = threadIdx.x, wid = tid >> 5, lid = tid & 31;
    const int b = blockIdx.y, qt = blockIdx.x;

    // All loads up front: Q (8 float4) + G hi/lo (8 uint4 each).
    const float4* qsrc = (const float4*)(dec + ((size_t)(b * 32 + qt) << 13));
    float4 q[8];
#pragma unroll
    for (int v = 0; v < 8; v++) q[v] = qsrc[tid + v * 256];
    const uint4* ghs = (const uint4*)(g_hiD + b * 8192);
    const uint4* gls = (const uint4*)(g_loD + b * 8192);
    uint4 gh[8], gl[8];
#pragma unroll
    for (int k = 0; k < 8; k++) { gh[k] = ghs[tid + k * 256]; gl[k] = gls[tid + k * 256]; }

    const bool q_s0 = (tid & 31) < 16;   // this thread's Q float4s are d<64
    const bool g_s0 = (tid & 8) == 0;    // this thread's G uint4s are d<64

    // Store helper lambdas (inlined).
#define STORE_Q()                                                              \
    do {                                                                       \
        _Pragma("unroll") for (int v = 0; v < 8; v++) {                        \
            int idx = tid + v * 256;                                           \
            int row = idx >> 5, d4 = idx & 31;                                 \
            uint32_t h0, l0, h1, l1;                                           \
            split2(q[v].x, q[v].y, h0, l0);                                    \
            split2(q[v].z, q[v].w, h1, l1);                                    \
            uint32_t off = (uint32_t)row * RSTRIDE + (uint32_t)d4 * 8;         \
            *(uint2*)(smem + QG_QHI + off) = make_uint2(h0, h1);               \
            *(uint2*)(smem + QG_QLO + off) = make_uint2(l0, l1);               \
        }                                                                      \
    } while (0)
#define STORE_G()                                                              \
    do {                                                                       \
        _Pragma("unroll") for (int k = 0; k < 8; k++) {                        \
            int i = tid + k * 256;      /* dense uint4 index, 0..2047 */       \
            int row = i >> 4, u = i & 15;                                      \
            uint32_t off = (uint32_t)row * RSTRIDE + (uint32_t)u * 16;         \
            *(uint4*)(smem + QG_GHI + off) = gh[k];                            \
            *(uint4*)(smem + QG_GLO + off) = gl[k];                            \
        }                                                                      \
    } while (0)

    if (q_s0) STORE_Q();
    if (g_s0) STORE_G();
    __syncthreads();

    const int wm = (wid >> 2) * 32, wn = (wid & 3) * 32;
    float acc[2][4][4];
#pragma unroll
    for (int mi = 0; mi < 2; mi++)
#pragma unroll
        for (int nj = 0; nj < 4; nj++)
#pragma unroll
            for (int r = 0; r < 4; r++) acc[mi][nj][r] = 0.0f;

    // Stage 1 stores (d>=64) overlap MMA on d = 0..63.
    if (!q_s0) STORE_Q();
    if (!g_s0) STORE_G();
    warp_gemm32<false>(sb + QG_QHI, sb + QG_QLO, sb + QG_GHI, sb + QG_GLO,
                       wm, wn, lid, 0, 4, acc);
    __syncthreads();
    warp_gemm32<false>(sb + QG_QHI, sb + QG_QLO, sb + QG_GHI, sb + QG_GLO,
                       wm, wn, lid, 4, 8, acc);

    warp_epilogue32(out + ((size_t)(b * 32 + qt) << 13), wm, wn, lid, acc);
#undef STORE_Q
#undef STORE_G
}

// ---------------------------------------------------------------------------
// Launch
// ---------------------------------------------------------------------------
extern "C" void kernel_launch(void* const* d_in, const int* in_sizes, int n_in,
                              void* d_out, int out_size) {
    const float* enc = (const float*)d_in[0];
    const float* dec = (const float*)d_in[1];
    float* out = (float*)d_out;

    cudaFuncSetAttribute(ete_hmma, cudaFuncAttributeMaxDynamicSharedMemorySize,
                         2 * PLANE128);
    cudaFuncSetAttribute(qg_hmma, cudaFuncAttributeMaxDynamicSharedMemorySize,
                         QG_SZ);

    ete_hmma<<<dim3(2 * NSPLIT, BB), 256, 2 * PLANE128>>>(enc);
    reduce_g<<<256, 256>>>();
    qg_hmma<<<dim3(32, BB), 256, QG_SZ>>>(dec, out);
}

// round 7
// speedup vs baseline: 1.0347x; 1.0196x over previous
#include <cuda_runtime.h>
#include <cuda_bf16.h>
#include <cstdint>

// LuongAttention: O[b] = (Q Eᵀ) E == Q (EᵀE).  G = EᵀE per batch (128x128).
// HMMA bf16 split-precision (hi·hi + hi·lo + lo·hi, fp32 accum, err ~6e-6).
// R7: NSPLIT=32 + occ3 for ete (more warps/SMSP), product-outer MMA ordering,
// and G stored in gmem directly as mma B-fragments (qg smem = Q planes only).

#define BB 8
#define NSPLIT 32
#define RSTRIDE 272                 // plane row stride, bytes
#define PLANE_T (64 * RSTRIDE)      // 17408 B: ete token-planes / qg Q-planes

__device__ float g_part[BB * NSPLIT * 128 * 128];   // 16 MB partials
// B-fragment layout: [b][n8tile 16][kstep 8][lane 32] = uint4
//   uint4 = { hi_b0, hi_b1, lo_b0, lo_b1 } for mma.m16n8k16 B operand.
__device__ uint4 g_frag[BB * 16 * 8 * 32];          // 512 KB

// ---------------- helpers ----------------
__device__ __forceinline__ uint32_t smem_u32(const void* p) {
    uint32_t a;
    asm("{ .reg .u64 t; cvta.to.shared.u64 t, %1; cvt.u32.u64 %0, t; }"
        : "=r"(a) : "l"(p));
    return a;
}
__device__ __forceinline__ void ldsm_x4(uint32_t (&r)[4], uint32_t addr) {
    asm volatile("ldmatrix.sync.aligned.m8n8.x4.shared.b16 {%0,%1,%2,%3}, [%4];"
                 : "=r"(r[0]), "=r"(r[1]), "=r"(r[2]), "=r"(r[3]) : "r"(addr));
}
__device__ __forceinline__ void ldsm_x4_t(uint32_t (&r)[4], uint32_t addr) {
    asm volatile("ldmatrix.sync.aligned.m8n8.x4.trans.shared.b16 {%0,%1,%2,%3}, [%4];"
                 : "=r"(r[0]), "=r"(r[1]), "=r"(r[2]), "=r"(r[3]) : "r"(addr));
}
__device__ __forceinline__ void mma16816(float (&d)[4], const uint32_t (&a)[4],
                                         uint32_t b0, uint32_t b1) {
    asm volatile(
        "mma.sync.aligned.m16n8k16.row.col.f32.bf16.bf16.f32 "
        "{%0,%1,%2,%3}, {%4,%5,%6,%7}, {%8,%9}, {%0,%1,%2,%3};"
        : "+f"(d[0]), "+f"(d[1]), "+f"(d[2]), "+f"(d[3])
        : "r"(a[0]), "r"(a[1]), "r"(a[2]), "r"(a[3]), "r"(b0), "r"(b1));
}
__device__ __forceinline__ void split2(float f0, float f1, uint32_t& hi, uint32_t& lo) {
    asm("cvt.rn.bf16x2.f32 %0, %1, %2;" : "=r"(hi) : "f"(f1), "f"(f0));
    float h0 = __uint_as_float(hi << 16);
    float h1 = __uint_as_float(hi & 0xffff0000u);
    asm("cvt.rn.bf16x2.f32 %0, %1, %2;" : "=r"(lo) : "f"(f1 - h1), "f"(f0 - h0));
}

__device__ __forceinline__ void warp_epilogue32(float* outp, int wm, int wn, int lid,
                                                float (&acc)[2][4][4]) {
    const int g = lid >> 2, tig = lid & 3;
#pragma unroll
    for (int mi = 0; mi < 2; mi++)
#pragma unroll
        for (int nj = 0; nj < 4; nj++) {
            const int row = wm + mi * 16 + g;
            const int col = wn + nj * 8 + 2 * tig;
            *(float2*)(outp + row * 128 + col) =
                make_float2(acc[mi][nj][0], acc[mi][nj][1]);
            *(float2*)(outp + (row + 8) * 128 + col) =
                make_float2(acc[mi][nj][2], acc[mi][nj][3]);
        }
}

// ---------------------------------------------------------------------------
// Kernel 1: partial EᵀE.  Chunk = 64 tokens; grid (2*NSPLIT, BB), bx=sp*2+half.
// Planes [t=64][d=128], ldmatrix.trans supplies the transpose.  occ 3.
// ---------------------------------------------------------------------------
__global__ __launch_bounds__(256, 3) void ete_hmma(const float* __restrict__ enc) {
    extern __shared__ char smem[];
    const uint32_t sb = smem_u32(smem);
    const int tid = threadIdx.x, wid = tid >> 5, lid = tid & 31;
    const int sp = blockIdx.x >> 1, half = blockIdx.x & 1, b = blockIdx.y;

    const float4* src = (const float4*)(enc + (size_t)(b * NSPLIT + sp) * (64 * 128));
    float4 q[8];
#pragma unroll
    for (int v = 0; v < 8; v++) q[v] = src[tid + v * 256];
#pragma unroll
    for (int v = 0; v < 8; v++) {
        int idx = tid + v * 256;
        int t = idx >> 5, d4 = idx & 31;
        uint32_t h0, l0, h1, l1;
        split2(q[v].x, q[v].y, h0, l0);
        split2(q[v].z, q[v].w, h1, l1);
        uint32_t off = (uint32_t)t * RSTRIDE + (uint32_t)d4 * 8;
        *(uint2*)(smem + off) = make_uint2(h0, h1);
        *(uint2*)(smem + PLANE_T + off) = make_uint2(l0, l1);
    }
    __syncthreads();

    const int wm = half * 64 + (wid >> 2) * 32, wn = (wid & 3) * 32;
    float acc[2][4][4];
#pragma unroll
    for (int mi = 0; mi < 2; mi++)
#pragma unroll
        for (int nj = 0; nj < 4; nj++)
#pragma unroll
            for (int r = 0; r < 4; r++) acc[mi][nj][r] = 0.0f;

    // Trans lane offsets (plane rows = k(token), cols = d).
    const uint32_t aRow = (lid & 7) + ((lid >> 4) << 3);
    const uint32_t aCol = ((lid >> 3) & 1) << 3;
    const uint32_t bRow = (lid & 7) + (((lid >> 3) & 1) << 3);
    const uint32_t bCol = (lid >> 4) << 3;

#pragma unroll
    for (int kk = 0; kk < 4; kk++) {
        const int k0 = kk * 16;
        uint32_t Ah[2][4], Al[2][4], Bh[2][4], Bl[2][4];
#pragma unroll
        for (int mi = 0; mi < 2; mi++) {
            uint32_t off = (uint32_t)(k0 + aRow) * RSTRIDE +
                           (uint32_t)(wm + mi * 16 + aCol) * 2;
            ldsm_x4_t(Ah[mi], sb + off);
            ldsm_x4_t(Al[mi], sb + PLANE_T + off);
        }
#pragma unroll
        for (int np = 0; np < 2; np++) {
            uint32_t off = (uint32_t)(k0 + bRow) * RSTRIDE +
                           (uint32_t)(wn + np * 16 + bCol) * 2;
            ldsm_x4_t(Bh[np], sb + off);
            ldsm_x4_t(Bl[np], sb + PLANE_T + off);
        }
        // Product-outer: 8 independent accs between same-acc reuses.
#pragma unroll
        for (int mi = 0; mi < 2; mi++)
#pragma unroll
            for (int nj = 0; nj < 4; nj++) {
                const int np = nj >> 1, pr = (nj & 1) << 1;
                mma16816(acc[mi][nj], Ah[mi], Bh[np][pr], Bh[np][pr + 1]);
            }
#pragma unroll
        for (int mi = 0; mi < 2; mi++)
#pragma unroll
            for (int nj = 0; nj < 4; nj++) {
                const int np = nj >> 1, pr = (nj & 1) << 1;
                mma16816(acc[mi][nj], Ah[mi], Bl[np][pr], Bl[np][pr + 1]);
            }
#pragma unroll
        for (int mi = 0; mi < 2; mi++)
#pragma unroll
            for (int nj = 0; nj < 4; nj++) {
                const int np = nj >> 1, pr = (nj & 1) << 1;
                mma16816(acc[mi][nj], Al[mi], Bh[np][pr], Bh[np][pr + 1]);
            }
    }
    warp_epilogue32(g_part + ((size_t)(b * NSPLIT + sp) << 14), wm, wn, lid, acc);
}

// ---------------------------------------------------------------------------
// Kernel 2: reduce partials; emit G rows as mma B-fragments (hi+lo packed).
// Thread (b, j, d2) produces G[j][2d2], G[j][2d2+1] = one bf16x2 pair.
// ---------------------------------------------------------------------------
__global__ __launch_bounds__(256) void reduce_g() {
    const int e2 = blockIdx.x * 256 + threadIdx.x;  // 0..65535
    const int b = e2 >> 13;
    const int r = e2 & 8191;
    const int j = r >> 6, d2 = r & 63;
    const float2* base =
        (const float2*)(g_part + ((size_t)(b * NSPLIT) << 14) + j * 128) + d2;
    float sx = 0.f, sy = 0.f;
#pragma unroll
    for (int sp = 0; sp < NSPLIT; sp++) {
        float2 v = base[(size_t)sp << 13];
        sx += v.x; sy += v.y;
    }
    uint32_t hi, lo;
    split2(sx, sy, hi, lo);
    // Fragment slot: n = j, k = 2*d2.
    const uint32_t lane = (uint32_t)(j & 7) * 4 + (d2 & 3);
    const uint32_t comp = (uint32_t)(d2 >> 2) & 1;            // b0 / b1
    const uint32_t slot = (((uint32_t)(b * 16 + (j >> 3)) * 8 + (d2 >> 3)) * 32 + lane);
    uint32_t* f = (uint32_t*)g_frag + slot * 4;
    f[comp] = hi;
    f[comp + 2] = lo;
}

// ---------------------------------------------------------------------------
// Kernel 3: O_tile(64x128) = Q_tile @ G[b].  Q via smem+ldsm; G fragments
// LDG.128 straight from gmem (L2-hot, 64 KB/batch) with 1-step prefetch.
// ---------------------------------------------------------------------------
__global__ __launch_bounds__(256, 2) void qg_hmma(const float* __restrict__ dec,
                                                  float* __restrict__ out) {
    extern __shared__ char smem[];
    const uint32_t sb = smem_u32(smem);
    const int tid = threadIdx.x, wid = tid >> 5, lid = tid & 31;
    const int b = blockIdx.y, qt = blockIdx.x;

    // Q tile [64 q][128 d] -> hi/lo planes (non-trans A layout: rows = q).
    const float4* qsrc = (const float4*)(dec + ((size_t)(b * 32 + qt) << 13));
    float4 q[8];
#pragma unroll
    for (int v = 0; v < 8; v++) q[v] = qsrc[tid + v * 256];
#pragma unroll
    for (int v = 0; v < 8; v++) {
        int idx = tid + v * 256;
        int row = idx >> 5, d4 = idx & 31;
        uint32_t h0, l0, h1, l1;
        split2(q[v].x, q[v].y, h0, l0);
        split2(q[v].z, q[v].w, h1, l1);
        uint32_t off = (uint32_t)row * RSTRIDE + (uint32_t)d4 * 8;
        *(uint2*)(smem + off) = make_uint2(h0, h1);
        *(uint2*)(smem + PLANE_T + off) = make_uint2(l0, l1);
    }
    __syncthreads();

    const int wm = (wid >> 2) * 32, wn = (wid & 3) * 32;
    const uint4* gf = g_frag + ((size_t)(b * 16 + (wn >> 3)) * 8) * 32 + lid;

    float acc[2][4][4];
#pragma unroll
    for (int mi = 0; mi < 2; mi++)
#pragma unroll
        for (int nj = 0; nj < 4; nj++)
#pragma unroll
            for (int r = 0; r < 4; r++) acc[mi][nj][r] = 0.0f;

    const uint32_t aRow = lid & 15;
    const uint32_t aCol = (lid >> 4) << 3;

    uint4 Gc[4];
#pragma unroll
    for (int nj = 0; nj < 4; nj++) Gc[nj] = gf[nj * 256];   // kk = 0

#pragma unroll
    for (int kk = 0; kk < 8; kk++) {
        const int k0 = kk * 16;
        uint4 Gn[4];
        if (kk < 7) {
#pragma unroll
            for (int nj = 0; nj < 4; nj++) Gn[nj] = gf[nj * 256 + (kk + 1) * 32];
        }
        uint32_t Ah[2][4], Al[2][4];
#pragma unroll
        for (int mi = 0; mi < 2; mi++) {
            uint32_t off = (uint32_t)(wm + mi * 16 + aRow) * RSTRIDE +
                           (uint32_t)(k0 + aCol) * 2;
            ldsm_x4(Ah[mi], sb + off);
            ldsm_x4(Al[mi], sb + PLANE_T + off);
        }
        // Product-outer ordering.
#pragma unroll
        for (int mi = 0; mi < 2; mi++)
#pragma unroll
            for (int nj = 0; nj < 4; nj++)
                mma16816(acc[mi][nj], Ah[mi], Gc[nj].x, Gc[nj].y);   // hi·hi
#pragma unroll
        for (int mi = 0; mi < 2; mi++)
#pragma unroll
            for (int nj = 0; nj < 4; nj++)
                mma16816(acc[mi][nj], Ah[mi], Gc[nj].z, Gc[nj].w);   // hi·lo
#pragma unroll
        for (int mi = 0; mi < 2; mi++)
#pragma unroll
            for (int nj = 0; nj < 4; nj++)
                mma16816(acc[mi][nj], Al[mi], Gc[nj].x, Gc[nj].y);   // lo·hi
#pragma unroll
        for (int nj = 0; nj < 4; nj++) Gc[nj] = Gn[nj];
    }
    warp_epilogue32(out + ((size_t)(b * 32 + qt) << 13), wm, wn, lid, acc);
}

// ---------------------------------------------------------------------------
// Launch
// ---------------------------------------------------------------------------
extern "C" void kernel_launch(void* const* d_in, const int* in_sizes, int n_in,
                              void* d_out, int out_size) {
    const float* enc = (const float*)d_in[0];
    const float* dec = (const float*)d_in[1];
    float* out = (float*)d_out;

    cudaFuncSetAttribute(ete_hmma, cudaFuncAttributeMaxDynamicSharedMemorySize,
                         2 * PLANE_T);
    cudaFuncSetAttribute(qg_hmma, cudaFuncAttributeMaxDynamicSharedMemorySize,
                         2 * PLANE_T);

    ete_hmma<<<dim3(2 * NSPLIT, BB), 256, 2 * PLANE_T>>>(enc);
    reduce_g<<<256, 256>>>();
    qg_hmma<<<dim3(32, BB), 256, 2 * PLANE_T>>>(dec, out);
}

// round 8
// speedup vs baseline: 1.1433x; 1.1050x over previous
#include <cuda_runtime.h>
#include <cuda_fp16.h>
#include <cstdint>

// LuongAttention: O[b] = (Q Eᵀ) E == Q (EᵀE).  G = EᵀE per batch (128x128).
// R8: fp16 split-precision with 2-term products — x·y ≈ hi_x·(hi_y + lo_y),
// dropping lo_x·hi_y (~2^-13 rel).  33% fewer MMA instructions than the bf16
// 3-term scheme; measured wall is MMA issue count.  B=8, T=2048, D=128.

#define BB 8
#define NSPLIT 32
#define RSTRIDE 272                 // plane row stride, bytes
#define PLANE_T (64 * RSTRIDE)      // 17408 B

__device__ float g_part[BB * NSPLIT * 128 * 128];   // 16 MB partials
// B-fragment layout: [b][n8tile 16][kstep 8][lane 32] = uint4
//   uint4 = { hi_b0, hi_b1, lo_b0, lo_b1 } (fp16x2 each).
__device__ uint4 g_frag[BB * 16 * 8 * 32];          // 512 KB

// ---------------- helpers ----------------
__device__ __forceinline__ uint32_t smem_u32(const void* p) {
    uint32_t a;
    asm("{ .reg .u64 t; cvta.to.shared.u64 t, %1; cvt.u32.u64 %0, t; }"
        : "=r"(a) : "l"(p));
    return a;
}
__device__ __forceinline__ void ldsm_x4(uint32_t (&r)[4], uint32_t addr) {
    asm volatile("ldmatrix.sync.aligned.m8n8.x4.shared.b16 {%0,%1,%2,%3}, [%4];"
                 : "=r"(r[0]), "=r"(r[1]), "=r"(r[2]), "=r"(r[3]) : "r"(addr));
}
__device__ __forceinline__ void ldsm_x4_t(uint32_t (&r)[4], uint32_t addr) {
    asm volatile("ldmatrix.sync.aligned.m8n8.x4.trans.shared.b16 {%0,%1,%2,%3}, [%4];"
                 : "=r"(r[0]), "=r"(r[1]), "=r"(r[2]), "=r"(r[3]) : "r"(addr));
}
__device__ __forceinline__ void mma16816(float (&d)[4], const uint32_t (&a)[4],
                                         uint32_t b0, uint32_t b1) {
    asm volatile(
        "mma.sync.aligned.m16n8k16.row.col.f32.f16.f16.f32 "
        "{%0,%1,%2,%3}, {%4,%5,%6,%7}, {%8,%9}, {%0,%1,%2,%3};"
        : "+f"(d[0]), "+f"(d[1]), "+f"(d[2]), "+f"(d[3])
        : "r"(a[0]), "r"(a[1]), "r"(a[2]), "r"(a[3]), "r"(b0), "r"(b1));
}
// fp16 hi/lo split of two fp32 values (f0 -> low half of packed pair).
__device__ __forceinline__ void split2h(float f0, float f1, uint32_t& hi, uint32_t& lo) {
    __half2 h = __floats2half2_rn(f0, f1);
    float2 hf = __half22float2(h);
    __half2 l = __floats2half2_rn(f0 - hf.x, f1 - hf.y);
    hi = *(uint32_t*)&h;
    lo = *(uint32_t*)&l;
}
__device__ __forceinline__ uint32_t pack2h(float f0, float f1) {
    __half2 h = __floats2half2_rn(f0, f1);
    return *(uint32_t*)&h;
}

__device__ __forceinline__ void warp_epilogue32(float* outp, int wm, int wn, int lid,
                                                float (&acc)[2][4][4]) {
    const int g = lid >> 2, tig = lid & 3;
#pragma unroll
    for (int mi = 0; mi < 2; mi++)
#pragma unroll
        for (int nj = 0; nj < 4; nj++) {
            const int row = wm + mi * 16 + g;
            const int col = wn + nj * 8 + 2 * tig;
            *(float2*)(outp + row * 128 + col) =
                make_float2(acc[mi][nj][0], acc[mi][nj][1]);
            *(float2*)(outp + (row + 8) * 128 + col) =
                make_float2(acc[mi][nj][2], acc[mi][nj][3]);
        }
}

// ---------------------------------------------------------------------------
// Kernel 1: partial EᵀE.  Chunk = 64 tokens; grid (2*NSPLIT, BB), bx=sp*2+half.
// Planes [t=64][d=128] fp16 hi/lo; ldmatrix.trans gives the transpose.
// G_sp ≈ Ehiᵀ(Ehi + Elo): A-side reads hi plane only.
// ---------------------------------------------------------------------------
__global__ __launch_bounds__(256, 3) void ete_hmma(const float* __restrict__ enc) {
    extern __shared__ char smem[];
    const uint32_t sb = smem_u32(smem);
    const int tid = threadIdx.x, wid = tid >> 5, lid = tid & 31;
    const int sp = blockIdx.x >> 1, half = blockIdx.x & 1, b = blockIdx.y;

    const float4* src = (const float4*)(enc + (size_t)(b * NSPLIT + sp) * (64 * 128));
    float4 q[8];
#pragma unroll
    for (int v = 0; v < 8; v++) q[v] = src[tid + v * 256];
#pragma unroll
    for (int v = 0; v < 8; v++) {
        int idx = tid + v * 256;
        int t = idx >> 5, d4 = idx & 31;
        uint32_t h0, l0, h1, l1;
        split2h(q[v].x, q[v].y, h0, l0);
        split2h(q[v].z, q[v].w, h1, l1);
        uint32_t off = (uint32_t)t * RSTRIDE + (uint32_t)d4 * 8;
        *(uint2*)(smem + off) = make_uint2(h0, h1);
        *(uint2*)(smem + PLANE_T + off) = make_uint2(l0, l1);
    }
    __syncthreads();

    const int wm = half * 64 + (wid >> 2) * 32, wn = (wid & 3) * 32;
    float acc[2][4][4];
#pragma unroll
    for (int mi = 0; mi < 2; mi++)
#pragma unroll
        for (int nj = 0; nj < 4; nj++)
#pragma unroll
            for (int r = 0; r < 4; r++) acc[mi][nj][r] = 0.0f;

    const uint32_t aRow = (lid & 7) + ((lid >> 4) << 3);
    const uint32_t aCol = ((lid >> 3) & 1) << 3;
    const uint32_t bRow = (lid & 7) + (((lid >> 3) & 1) << 3);
    const uint32_t bCol = (lid >> 4) << 3;

#pragma unroll
    for (int kk = 0; kk < 4; kk++) {
        const int k0 = kk * 16;
        uint32_t Ah[2][4], Bh[2][4], Bl[2][4];
#pragma unroll
        for (int mi = 0; mi < 2; mi++) {
            uint32_t off = (uint32_t)(k0 + aRow) * RSTRIDE +
                           (uint32_t)(wm + mi * 16 + aCol) * 2;
            ldsm_x4_t(Ah[mi], sb + off);
        }
#pragma unroll
        for (int np = 0; np < 2; np++) {
            uint32_t off = (uint32_t)(k0 + bRow) * RSTRIDE +
                           (uint32_t)(wn + np * 16 + bCol) * 2;
            ldsm_x4_t(Bh[np], sb + off);
            ldsm_x4_t(Bl[np], sb + PLANE_T + off);
        }
        // Product-outer: 8 independent accs between same-acc reuses.
#pragma unroll
        for (int mi = 0; mi < 2; mi++)
#pragma unroll
            for (int nj = 0; nj < 4; nj++) {
                const int np = nj >> 1, pr = (nj & 1) << 1;
                mma16816(acc[mi][nj], Ah[mi], Bh[np][pr], Bh[np][pr + 1]);
            }
#pragma unroll
        for (int mi = 0; mi < 2; mi++)
#pragma unroll
            for (int nj = 0; nj < 4; nj++) {
                const int np = nj >> 1, pr = (nj & 1) << 1;
                mma16816(acc[mi][nj], Ah[mi], Bl[np][pr], Bl[np][pr + 1]);
            }
    }
    warp_epilogue32(g_part + ((size_t)(b * NSPLIT + sp) << 14), wm, wn, lid, acc);
}

// ---------------------------------------------------------------------------
// Kernel 2: reduce partials; emit G rows as fp16 mma B-fragments (hi+lo).
// ---------------------------------------------------------------------------
__global__ __launch_bounds__(256) void reduce_g() {
    const int e2 = blockIdx.x * 256 + threadIdx.x;  // 0..65535
    const int b = e2 >> 13;
    const int r = e2 & 8191;
    const int j = r >> 6, d2 = r & 63;
    const float2* base =
        (const float2*)(g_part + ((size_t)(b * NSPLIT) << 14) + j * 128) + d2;
    float sx = 0.f, sy = 0.f;
#pragma unroll
    for (int sp = 0; sp < NSPLIT; sp++) {
        float2 v = base[(size_t)sp << 13];
        sx += v.x; sy += v.y;
    }
    uint32_t hi, lo;
    split2h(sx, sy, hi, lo);
    const uint32_t lane = (uint32_t)(j & 7) * 4 + (d2 & 3);
    const uint32_t comp = (uint32_t)(d2 >> 2) & 1;
    const uint32_t slot = (((uint32_t)(b * 16 + (j >> 3)) * 8 + (d2 >> 3)) * 32 + lane);
    uint32_t* f = (uint32_t*)g_frag + slot * 4;
    f[comp] = hi;
    f[comp + 2] = lo;
}

// ---------------------------------------------------------------------------
// Kernel 3: O_tile(64x128) = Qhi_tile @ (Ghi + Glo).  Q hi plane only in smem;
// G fragments LDG.128 from gmem (L2-hot) with 1-step prefetch.
// ---------------------------------------------------------------------------
__global__ __launch_bounds__(256, 3) void qg_hmma(const float* __restrict__ dec,
                                                  float* __restrict__ out) {
    extern __shared__ char smem[];
    const uint32_t sb = smem_u32(smem);
    const int tid = threadIdx.x, wid = tid >> 5, lid = tid & 31;
    const int b = blockIdx.y, qt = blockIdx.x;

    // Q tile [64 q][128 d] -> hi plane only.
    const float4* qsrc = (const float4*)(dec + ((size_t)(b * 32 + qt) << 13));
    float4 q[8];
#pragma unroll
    for (int v = 0; v < 8; v++) q[v] = qsrc[tid + v * 256];
#pragma unroll
    for (int v = 0; v < 8; v++) {
        int idx = tid + v * 256;
        int row = idx >> 5, d4 = idx & 31;
        uint32_t off = (uint32_t)row * RSTRIDE + (uint32_t)d4 * 8;
        *(uint2*)(smem + off) =
            make_uint2(pack2h(q[v].x, q[v].y), pack2h(q[v].z, q[v].w));
    }
    __syncthreads();

    const int wm = (wid >> 2) * 32, wn = (wid & 3) * 32;
    const uint4* gf = g_frag + ((size_t)(b * 16 + (wn >> 3)) * 8) * 32 + lid;

    float acc[2][4][4];
#pragma unroll
    for (int mi = 0; mi < 2; mi++)
#pragma unroll
        for (int nj = 0; nj < 4; nj++)
#pragma unroll
            for (int r = 0; r < 4; r++) acc[mi][nj][r] = 0.0f;

    const uint32_t aRow = lid & 15;
    const uint32_t aCol = (lid >> 4) << 3;

    uint4 Gc[4];
#pragma unroll
    for (int nj = 0; nj < 4; nj++) Gc[nj] = gf[nj * 256];   // kk = 0

#pragma unroll
    for (int kk = 0; kk < 8; kk++) {
        const int k0 = kk * 16;
        uint4 Gn[4];
        if (kk < 7) {
#pragma unroll
            for (int nj = 0; nj < 4; nj++) Gn[nj] = gf[nj * 256 + (kk + 1) * 32];
        }
        uint32_t Ah[2][4];
#pragma unroll
        for (int mi = 0; mi < 2; mi++) {
            uint32_t off = (uint32_t)(wm + mi * 16 + aRow) * RSTRIDE +
                           (uint32_t)(k0 + aCol) * 2;
            ldsm_x4(Ah[mi], sb + off);
        }
#pragma unroll
        for (int mi = 0; mi < 2; mi++)
#pragma unroll
            for (int nj = 0; nj < 4; nj++)
                mma16816(acc[mi][nj], Ah[mi], Gc[nj].x, Gc[nj].y);   // hiQ·hiG
#pragma unroll
        for (int mi = 0; mi < 2; mi++)
#pragma unroll
            for (int nj = 0; nj < 4; nj++)
                mma16816(acc[mi][nj], Ah[mi], Gc[nj].z, Gc[nj].w);   // hiQ·loG
#pragma unroll
        for (int nj = 0; nj < 4; nj++) Gc[nj] = Gn[nj];
    }
    warp_epilogue32(out + ((size_t)(b * 32 + qt) << 13), wm, wn, lid, acc);
}

// ---------------------------------------------------------------------------
// Launch
// ---------------------------------------------------------------------------
extern "C" void kernel_launch(void* const* d_in, const int* in_sizes, int n_in,
                              void* d_out, int out_size) {
    const float* enc = (const float*)d_in[0];
    const float* dec = (const float*)d_in[1];
    float* out = (float*)d_out;

    cudaFuncSetAttribute(ete_hmma, cudaFuncAttributeMaxDynamicSharedMemorySize,
                         2 * PLANE_T);
    cudaFuncSetAttribute(qg_hmma, cudaFuncAttributeMaxDynamicSharedMemorySize,
                         PLANE_T);

    ete_hmma<<<dim3(2 * NSPLIT, BB), 256, 2 * PLANE_T>>>(enc);
    reduce_g<<<256, 256>>>();
    qg_hmma<<<dim3(32, BB), 256, PLANE_T>>>(dec, out);
}

// round 9
// speedup vs baseline: 1.2185x; 1.0657x over previous
#include <cuda_runtime.h>
#include <cuda_fp16.h>
#include <cstdint>

// LuongAttention: O[b] = (Q Eᵀ) E == Q (EᵀE).  G = EᵀE per batch (128x128).
// fp16 split-precision 2-term products: x·y ≈ hi_x·(hi_y + lo_y) (err ~2e-4).
// R9: NSPLIT=16 with per-CTA K=128 double-buffered over two 64-token stages
// (stage-1 DRAM loads hide under stage-0 MMAs); half the partial traffic;
// 2-deep G-fragment prefetch in qg.  B=8, T=2048, D=128.

#define BB 8
#define NSPLIT 16
#define RSTRIDE 272                 // plane row stride, bytes
#define PLANE_T (64 * RSTRIDE)      // 17408 B
#define STAGE_SZ (2 * PLANE_T)      // hi + lo planes per stage

__device__ float g_part[BB * NSPLIT * 128 * 128];   // 8 MB partials
// B-fragment layout: [b][n8tile 16][kstep 8][lane 32] = uint4
//   uint4 = { hi_b0, hi_b1, lo_b0, lo_b1 } (fp16x2 each).
__device__ uint4 g_frag[BB * 16 * 8 * 32];          // 512 KB

// ---------------- helpers ----------------
__device__ __forceinline__ uint32_t smem_u32(const void* p) {
    uint32_t a;
    asm("{ .reg .u64 t; cvta.to.shared.u64 t, %1; cvt.u32.u64 %0, t; }"
        : "=r"(a) : "l"(p));
    return a;
}
__device__ __forceinline__ void ldsm_x4(uint32_t (&r)[4], uint32_t addr) {
    asm volatile("ldmatrix.sync.aligned.m8n8.x4.shared.b16 {%0,%1,%2,%3}, [%4];"
                 : "=r"(r[0]), "=r"(r[1]), "=r"(r[2]), "=r"(r[3]) : "r"(addr));
}
__device__ __forceinline__ void ldsm_x4_t(uint32_t (&r)[4], uint32_t addr) {
    asm volatile("ldmatrix.sync.aligned.m8n8.x4.trans.shared.b16 {%0,%1,%2,%3}, [%4];"
                 : "=r"(r[0]), "=r"(r[1]), "=r"(r[2]), "=r"(r[3]) : "r"(addr));
}
__device__ __forceinline__ void mma16816(float (&d)[4], const uint32_t (&a)[4],
                                         uint32_t b0, uint32_t b1) {
    asm volatile(
        "mma.sync.aligned.m16n8k16.row.col.f32.f16.f16.f32 "
        "{%0,%1,%2,%3}, {%4,%5,%6,%7}, {%8,%9}, {%0,%1,%2,%3};"
        : "+f"(d[0]), "+f"(d[1]), "+f"(d[2]), "+f"(d[3])
        : "r"(a[0]), "r"(a[1]), "r"(a[2]), "r"(a[3]), "r"(b0), "r"(b1));
}
__device__ __forceinline__ void split2h(float f0, float f1, uint32_t& hi, uint32_t& lo) {
    __half2 h = __floats2half2_rn(f0, f1);
    float2 hf = __half22float2(h);
    __half2 l = __floats2half2_rn(f0 - hf.x, f1 - hf.y);
    hi = *(uint32_t*)&h;
    lo = *(uint32_t*)&l;
}
__device__ __forceinline__ uint32_t pack2h(float f0, float f1) {
    __half2 h = __floats2half2_rn(f0, f1);
    return *(uint32_t*)&h;
}

__device__ __forceinline__ void warp_epilogue32(float* outp, int wm, int wn, int lid,
                                                float (&acc)[2][4][4]) {
    const int g = lid >> 2, tig = lid & 3;
#pragma unroll
    for (int mi = 0; mi < 2; mi++)
#pragma unroll
        for (int nj = 0; nj < 4; nj++) {
            const int row = wm + mi * 16 + g;
            const int col = wn + nj * 8 + 2 * tig;
            *(float2*)(outp + row * 128 + col) =
                make_float2(acc[mi][nj][0], acc[mi][nj][1]);
            *(float2*)(outp + (row + 8) * 128 + col) =
                make_float2(acc[mi][nj][2], acc[mi][nj][3]);
        }
}

// Split a register batch into stage planes.
__device__ __forceinline__ void stage_store(char* smem, int stage, int tid,
                                            const float4* q) {
    char* base = smem + stage * STAGE_SZ;
#pragma unroll
    for (int v = 0; v < 8; v++) {
        int idx = tid + v * 256;
        int t = idx >> 5, d4 = idx & 31;
        uint32_t h0, l0, h1, l1;
        split2h(q[v].x, q[v].y, h0, l0);
        split2h(q[v].z, q[v].w, h1, l1);
        uint32_t off = (uint32_t)t * RSTRIDE + (uint32_t)d4 * 8;
        *(uint2*)(base + off) = make_uint2(h0, h1);
        *(uint2*)(base + PLANE_T + off) = make_uint2(l0, l1);
    }
}

// MMA over one 64-token stage (4 ksteps), trans layout, 2-term products.
__device__ __forceinline__ void stage_mma(uint32_t sbase, int wm, int wn, int lid,
                                          float (&acc)[2][4][4]) {
    const uint32_t aRow = (lid & 7) + ((lid >> 4) << 3);
    const uint32_t aCol = ((lid >> 3) & 1) << 3;
    const uint32_t bRow = (lid & 7) + (((lid >> 3) & 1) << 3);
    const uint32_t bCol = (lid >> 4) << 3;

#pragma unroll
    for (int kk = 0; kk < 4; kk++) {
        const int k0 = kk * 16;
        uint32_t Ah[2][4], Bh[2][4], Bl[2][4];
#pragma unroll
        for (int mi = 0; mi < 2; mi++) {
            uint32_t off = (uint32_t)(k0 + aRow) * RSTRIDE +
                           (uint32_t)(wm + mi * 16 + aCol) * 2;
            ldsm_x4_t(Ah[mi], sbase + off);
        }
#pragma unroll
        for (int np = 0; np < 2; np++) {
            uint32_t off = (uint32_t)(k0 + bRow) * RSTRIDE +
                           (uint32_t)(wn + np * 16 + bCol) * 2;
            ldsm_x4_t(Bh[np], sbase + off);
            ldsm_x4_t(Bl[np], sbase + PLANE_T + off);
        }
#pragma unroll
        for (int mi = 0; mi < 2; mi++)
#pragma unroll
            for (int nj = 0; nj < 4; nj++) {
                const int np = nj >> 1, pr = (nj & 1) << 1;
                mma16816(acc[mi][nj], Ah[mi], Bh[np][pr], Bh[np][pr + 1]);
            }
#pragma unroll
        for (int mi = 0; mi < 2; mi++)
#pragma unroll
            for (int nj = 0; nj < 4; nj++) {
                const int np = nj >> 1, pr = (nj & 1) << 1;
                mma16816(acc[mi][nj], Ah[mi], Bl[np][pr], Bl[np][pr + 1]);
            }
    }
}

// ---------------------------------------------------------------------------
// Kernel 1: partial EᵀE.  CTA (sp, half): K = 128 tokens in two 64-token
// stages, double-buffered; stage-1 LDG overlaps stage-0 MMA.
// Grid (2*NSPLIT, BB); bx = sp*2 + half.
// ---------------------------------------------------------------------------
__global__ __launch_bounds__(256) void ete_hmma(const float* __restrict__ enc) {
    extern __shared__ char smem[];
    const uint32_t sb = smem_u32(smem);
    const int tid = threadIdx.x, wid = tid >> 5, lid = tid & 31;
    const int sp = blockIdx.x >> 1, half = blockIdx.x & 1, b = blockIdx.y;

    const float4* src =
        (const float4*)(enc + (size_t)(b * NSPLIT + sp) * (128 * 128));

    // Stage 0 loads + stores.
    float4 q0[8];
#pragma unroll
    for (int v = 0; v < 8; v++) q0[v] = src[tid + v * 256];
    stage_store(smem, 0, tid, q0);
    __syncthreads();

    // Stage 1 loads issued NOW — they fly while stage-0 MMAs run.
    float4 q1[8];
#pragma unroll
    for (int v = 0; v < 8; v++) q1[v] = src[2048 + tid + v * 256];

    const int wm = half * 64 + (wid >> 2) * 32, wn = (wid & 3) * 32;
    float acc[2][4][4];
#pragma unroll
    for (int mi = 0; mi < 2; mi++)
#pragma unroll
        for (int nj = 0; nj < 4; nj++)
#pragma unroll
            for (int r = 0; r < 4; r++) acc[mi][nj][r] = 0.0f;

    stage_mma(sb, wm, wn, lid, acc);           // tokens 0..63

    stage_store(smem, 1, tid, q1);
    __syncthreads();

    stage_mma(sb + STAGE_SZ, wm, wn, lid, acc); // tokens 64..127

    warp_epilogue32(g_part + ((size_t)(b * NSPLIT + sp) << 14), wm, wn, lid, acc);
}

// ---------------------------------------------------------------------------
// Kernel 2: reduce partials; emit G rows as fp16 mma B-fragments (hi+lo).
// ---------------------------------------------------------------------------
__global__ __launch_bounds__(256) void reduce_g() {
    const int e2 = blockIdx.x * 256 + threadIdx.x;  // 0..65535
    const int b = e2 >> 13;
    const int r = e2 & 8191;
    const int j = r >> 6, d2 = r & 63;
    const float2* base =
        (const float2*)(g_part + ((size_t)b << 18) + j * 128) + d2;
    float sx = 0.f, sy = 0.f;
#pragma unroll
    for (int sp = 0; sp < NSPLIT; sp++) {
        float2 v = base[(size_t)sp << 13];
        sx += v.x; sy += v.y;
    }
    uint32_t hi, lo;
    split2h(sx, sy, hi, lo);
    const uint32_t lane = (uint32_t)(j & 7) * 4 + (d2 & 3);
    const uint32_t comp = (uint32_t)(d2 >> 2) & 1;
    const uint32_t slot = (((uint32_t)(b * 16 + (j >> 3)) * 8 + (d2 >> 3)) * 32 + lane);
    uint32_t* f = (uint32_t*)g_frag + slot * 4;
    f[comp] = hi;
    f[comp + 2] = lo;
}

// ---------------------------------------------------------------------------
// Kernel 3: O_tile(64x128) = Qhi_tile @ (Ghi + Glo).  Q hi plane in smem;
// G fragments LDG.128 from gmem (L2-hot) with 2-deep prefetch.
// ---------------------------------------------------------------------------
__global__ __launch_bounds__(256, 3) void qg_hmma(const float* __restrict__ dec,
                                                  float* __restrict__ out) {
    extern __shared__ char smem[];
    const uint32_t sb = smem_u32(smem);
    const int tid = threadIdx.x, wid = tid >> 5, lid = tid & 31;
    const int b = blockIdx.y, qt = blockIdx.x;

    // Q tile [64 q][128 d] -> hi plane only.
    const float4* qsrc = (const float4*)(dec + ((size_t)(b * 32 + qt) << 13));
    float4 q[8];
#pragma unroll
    for (int v = 0; v < 8; v++) q[v] = qsrc[tid + v * 256];
#pragma unroll
    for (int v = 0; v < 8; v++) {
        int idx = tid + v * 256;
        int row = idx >> 5, d4 = idx & 31;
        uint32_t off = (uint32_t)row * RSTRIDE + (uint32_t)d4 * 8;
        *(uint2*)(smem + off) =
            make_uint2(pack2h(q[v].x, q[v].y), pack2h(q[v].z, q[v].w));
    }
    __syncthreads();

    const int wm = (wid >> 2) * 32, wn = (wid & 3) * 32;
    const uint4* gf = g_frag + ((size_t)(b * 16 + (wn >> 3)) * 8) * 32 + lid;

    float acc[2][4][4];
#pragma unroll
    for (int mi = 0; mi < 2; mi++)
#pragma unroll
        for (int nj = 0; nj < 4; nj++)
#pragma unroll
            for (int r = 0; r < 4; r++) acc[mi][nj][r] = 0.0f;

    const uint32_t aRow = lid & 15;
    const uint32_t aCol = (lid >> 4) << 3;

    // Double-buffered fragments, 2-deep prefetch.
    uint4 Gb[2][4];
#pragma unroll
    for (int nj = 0; nj < 4; nj++) Gb[0][nj] = gf[nj * 256];
#pragma unroll
    for (int nj = 0; nj < 4; nj++) Gb[1][nj] = gf[nj * 256 + 32];

#pragma unroll
    for (int kk = 0; kk < 8; kk++) {
        const int k0 = kk * 16;
        const int buf = kk & 1;
        uint32_t Ah[2][4];
#pragma unroll
        for (int mi = 0; mi < 2; mi++) {
            uint32_t off = (uint32_t)(wm + mi * 16 + aRow) * RSTRIDE +
                           (uint32_t)(k0 + aCol) * 2;
            ldsm_x4(Ah[mi], sb + off);
        }
#pragma unroll
        for (int mi = 0; mi < 2; mi++)
#pragma unroll
            for (int nj = 0; nj < 4; nj++)
                mma16816(acc[mi][nj], Ah[mi], Gb[buf][nj].x, Gb[buf][nj].y);
#pragma unroll
        for (int mi = 0; mi < 2; mi++)
#pragma unroll
            for (int nj = 0; nj < 4; nj++)
                mma16816(acc[mi][nj], Ah[mi], Gb[buf][nj].z, Gb[buf][nj].w);
        if (kk < 6) {
#pragma unroll
            for (int nj = 0; nj < 4; nj++)
                Gb[buf][nj] = gf[nj * 256 + (kk + 2) * 32];
        }
    }
    warp_epilogue32(out + ((size_t)(b * 32 + qt) << 13), wm, wn, lid, acc);
}

// ---------------------------------------------------------------------------
// Launch
// ---------------------------------------------------------------------------
extern "C" void kernel_launch(void* const* d_in, const int* in_sizes, int n_in,
                              void* d_out, int out_size) {
    const float* enc = (const float*)d_in[0];
    const float* dec = (const float*)d_in[1];
    float* out = (float*)d_out;

    cudaFuncSetAttribute(ete_hmma, cudaFuncAttributeMaxDynamicSharedMemorySize,
                         2 * STAGE_SZ);
    cudaFuncSetAttribute(qg_hmma, cudaFuncAttributeMaxDynamicSharedMemorySize,
                         PLANE_T);

    ete_hmma<<<dim3(2 * NSPLIT, BB), 256, 2 * STAGE_SZ>>>(enc);
    reduce_g<<<256, 256>>>();
    qg_hmma<<<dim3(32, BB), 256, PLANE_T>>>(dec, out);
}